// round 5
// baseline (speedup 1.0000x reference)
#include <cuda_runtime.h>
#include <cuda_bf16.h>
#include <cstdint>

// Problem constants
#define B_  2
#define S_  2048
#define D_  1024
#define H_  16
#define HD_ 64
#define M_  (B_ * S_)          // 4096 tokens

// ---------------------------------------------------------------------------
// Scratch (allocation-free rule: __device__ globals)
// ---------------------------------------------------------------------------
__device__ float g_q[M_ * D_];
__device__ float g_k[M_ * D_];
__device__ float g_v[M_ * D_];
__device__ float g_ctx[M_ * D_];
__device__ __nv_bfloat16 g_ahi[M_ * D_];   // activation split hi  (x, then ctx)
__device__ __nv_bfloat16 g_alo[M_ * D_];   // activation split lo
__device__ __nv_bfloat16 g_bhi[D_ * D_];   // weight split hi, transposed [N,K]
__device__ __nv_bfloat16 g_blo[D_ * D_];   // weight split lo, transposed [N,K]

// ---------------------------------------------------------------------------
// PTX helpers (sm_80-era instructions only: compute_103 target rejects tcgen05)
// ---------------------------------------------------------------------------
__device__ __forceinline__ uint32_t smem_u32(const void* p) {
    uint32_t a;
    asm("{ .reg .u64 t; cvta.to.shared.u64 t, %1; cvt.u32.u64 %0, t; }" : "=r"(a) : "l"(p));
    return a;
}

__device__ __forceinline__ void ldsm_x4(uint32_t* r, uint32_t addr) {
    asm volatile("ldmatrix.sync.aligned.m8n8.x4.shared.b16 {%0,%1,%2,%3}, [%4];"
                 : "=r"(r[0]), "=r"(r[1]), "=r"(r[2]), "=r"(r[3]) : "r"(addr));
}

__device__ __forceinline__ void mma16816(float* c, const uint32_t* a,
                                         uint32_t b0, uint32_t b1) {
    asm volatile("mma.sync.aligned.m16n8k16.row.col.f32.bf16.bf16.f32 "
                 "{%0,%1,%2,%3}, {%4,%5,%6,%7}, {%8,%9}, {%0,%1,%2,%3};"
                 : "+f"(c[0]), "+f"(c[1]), "+f"(c[2]), "+f"(c[3])
                 : "r"(a[0]), "r"(a[1]), "r"(a[2]), "r"(a[3]), "r"(b0), "r"(b1));
}

__device__ __forceinline__ void cp16(uint32_t dst, const void* src) {
    asm volatile("cp.async.cg.shared.global [%0], [%1], 16;" :: "r"(dst), "l"(src) : "memory");
}
#define CP_COMMIT() asm volatile("cp.async.commit_group;" ::: "memory")
#define CP_WAIT0()  asm volatile("cp.async.wait_group 0;" ::: "memory")
#define CP_WAIT1()  asm volatile("cp.async.wait_group 1;" ::: "memory")

// ---------------------------------------------------------------------------
// Split kernels: fp32 -> (bf16 hi, bf16 lo), lo = bf16(x - float(hi))
// ---------------------------------------------------------------------------
__global__ __launch_bounds__(256)
void split_act_kernel(const float* __restrict__ in,
                      __nv_bfloat16* __restrict__ hi, __nv_bfloat16* __restrict__ lo)
{
    const int idx = (blockIdx.x * 256 + threadIdx.x) * 4;
    float4 v = *(const float4*)(in + idx);
    __nv_bfloat162 h01 = __floats2bfloat162_rn(v.x, v.y);
    __nv_bfloat162 h23 = __floats2bfloat162_rn(v.z, v.w);
    float2 f01 = __bfloat1622float2(h01);
    float2 f23 = __bfloat1622float2(h23);
    __nv_bfloat162 l01 = __floats2bfloat162_rn(v.x - f01.x, v.y - f01.y);
    __nv_bfloat162 l23 = __floats2bfloat162_rn(v.z - f23.x, v.w - f23.y);
    *(__nv_bfloat162*)(hi + idx)     = h01;
    *(__nv_bfloat162*)(hi + idx + 2) = h23;
    *(__nv_bfloat162*)(lo + idx)     = l01;
    *(__nv_bfloat162*)(lo + idx + 2) = l23;
}

// W[K=1024, N=1024] fp32 -> hi/lo [N, K] bf16 (transpose + split)
__global__ __launch_bounds__(256)
void split_w_kernel(const float* __restrict__ W,
                    __nv_bfloat16* __restrict__ hi, __nv_bfloat16* __restrict__ lo)
{
    __shared__ float t[32][33];
    const int tx = threadIdx.x, ty = threadIdx.y;      // 32 x 8
    const int n0 = blockIdx.x * 32, k0 = blockIdx.y * 32;
#pragma unroll
    for (int r = 0; r < 32; r += 8)
        t[ty + r][tx] = W[(size_t)(k0 + ty + r) * D_ + n0 + tx];
    __syncthreads();
#pragma unroll
    for (int r = 0; r < 32; r += 8) {
        const float v = t[tx][ty + r];
        const __nv_bfloat16 h = __float2bfloat16(v);
        const __nv_bfloat16 l = __float2bfloat16(v - __bfloat162float(h));
        const size_t o = (size_t)(n0 + ty + r) * D_ + k0 + tx;
        hi[o] = h; lo[o] = l;
    }
}

// ---------------------------------------------------------------------------
// mma.sync bf16x3 GEMM:  C[M,N] = Ahi@Bhi^T + Ahi@Blo^T + Alo@Bhi^T + bias
// CTA tile 128x128, BK=64, 2-stage cp.async pipeline (load k+1 || compute k).
// 8 warps (2m x 4n), warp tile 64x32, fp32 register accumulators.
// ---------------------------------------------------------------------------
#define GSM_A_HI 0
#define GSM_A_LO 16384
#define GSM_B_HI 32768
#define GSM_B_LO 49152
#define G_STAGE  65536
#define G_SMEM   (2 * G_STAGE + 1024)

__global__ __launch_bounds__(256, 1)
void gemm_mma_bf16x3(const __nv_bfloat16* __restrict__ Ahi, const __nv_bfloat16* __restrict__ Alo,
                     const __nv_bfloat16* __restrict__ Bhi, const __nv_bfloat16* __restrict__ Blo,
                     const float* __restrict__ bias, float* __restrict__ C)
{
    extern __shared__ char smraw[];
    const uint32_t raw = smem_u32(smraw);
    const uint32_t org = (raw + 1023u) & ~1023u;      // 1024-aligned for swizzle

    const int tid  = threadIdx.x;
    const int lane = tid & 31;
    const int wid  = tid >> 5;
    const int wm   = wid >> 2;            // 0..1
    const int wn   = wid & 3;             // 0..3
    const int bm = blockIdx.y * 128, bn = blockIdx.x * 128;

    const int grp = lane >> 3, lr = lane & 7;

    // ldmatrix row-base offsets (relative; add stage + matrix offset at use)
    uint32_t a_base[4]; int a_xr[4];
#pragma unroll
    for (int mt = 0; mt < 4; mt++) {
        const int r = wm * 64 + mt * 16 + ((grp & 1) << 3) + lr;
        a_base[mt] = org + (uint32_t)(r << 7);
        a_xr[mt] = r & 7;
    }
    const int cA = grp >> 1;

    uint32_t b_base[2]; int b_xr[2];
#pragma unroll
    for (int np = 0; np < 2; np++) {
        const int r = wn * 32 + np * 16 + ((grp >> 1) << 3) + lr;
        b_base[np] = org + (uint32_t)(r << 7);
        b_xr[np] = r & 7;
    }
    const int cB = grp & 1;

    float acc[4][4][4];
#pragma unroll
    for (int i = 0; i < 4; i++)
#pragma unroll
        for (int j = 0; j < 4; j++)
#pragma unroll
            for (int q = 0; q < 4; q++) acc[i][j][q] = 0.f;

    // cp.async store-side constants
    const int srow0 = tid >> 3;            // + 32*i
    const int scol  = tid & 7;             // 16B chunk
    const uint32_t cxor = (uint32_t)((scol ^ ((tid >> 3) & 7)) << 4);

#define G_ISSUE(KT) do {                                                       \
    const int _k0 = (KT) * 64;                                                 \
    const uint32_t stg = org + ((KT) & 1) * G_STAGE;                           \
    _Pragma("unroll")                                                          \
    for (int i = 0; i < 4; i++) {                                              \
        const int row = srow0 + 32 * i;                                        \
        const uint32_t doff = (uint32_t)(row << 7) + cxor;                     \
        const size_t ea = (size_t)(bm + row) * D_ + _k0 + scol * 8;            \
        const size_t eb = (size_t)(bn + row) * D_ + _k0 + scol * 8;            \
        cp16(stg + GSM_A_HI + doff, Ahi + ea);                                 \
        cp16(stg + GSM_A_LO + doff, Alo + ea);                                 \
        cp16(stg + GSM_B_HI + doff, Bhi + eb);                                 \
        cp16(stg + GSM_B_LO + doff, Blo + eb);                                 \
    }                                                                          \
    CP_COMMIT();                                                               \
} while (0)

    G_ISSUE(0);

    for (int kt = 0; kt < 16; kt++) {
        if (kt < 15) { G_ISSUE(kt + 1); CP_WAIT1(); }
        else         { CP_WAIT0(); }
        __syncthreads();

        const uint32_t stg = (uint32_t)((kt & 1) * G_STAGE);
#pragma unroll
        for (int t = 0; t < 3; t++) {
            const uint32_t aoff = stg + ((t == 2) ? GSM_A_LO : GSM_A_HI);
            const uint32_t boff = stg + ((t == 1) ? GSM_B_LO : GSM_B_HI);
#pragma unroll
            for (int ks = 0; ks < 4; ks++) {
                uint32_t af[4][4];
#pragma unroll
                for (int mt = 0; mt < 4; mt++) {
                    const int cc = ks * 2 + cA;
                    ldsm_x4(af[mt], a_base[mt] + aoff + (uint32_t)((cc ^ a_xr[mt]) << 4));
                }
                uint32_t bf[2][4];
#pragma unroll
                for (int np = 0; np < 2; np++) {
                    const int cc = ks * 2 + cB;
                    ldsm_x4(bf[np], b_base[np] + boff + (uint32_t)((cc ^ b_xr[np]) << 4));
                }
#pragma unroll
                for (int mt = 0; mt < 4; mt++)
#pragma unroll
                    for (int nt = 0; nt < 4; nt++)
                        mma16816(acc[mt][nt], af[mt],
                                 bf[nt >> 1][(nt & 1) * 2], bf[nt >> 1][(nt & 1) * 2 + 1]);
            }
        }
        __syncthreads();   // computing done before issue overwrites this stage
    }

    // Epilogue: fragment -> gmem with bias
#pragma unroll
    for (int mt = 0; mt < 4; mt++) {
        const int r0 = bm + wm * 64 + mt * 16 + (lane >> 2);
#pragma unroll
        for (int nt = 0; nt < 4; nt++) {
            const int c0 = bn + wn * 32 + nt * 8 + ((lane & 3) << 1);
            const float bx = bias[c0], by = bias[c0 + 1];
            float2 o0, o1;
            o0.x = acc[mt][nt][0] + bx; o0.y = acc[mt][nt][1] + by;
            o1.x = acc[mt][nt][2] + bx; o1.y = acc[mt][nt][3] + by;
            *(float2*)(C + (size_t)r0 * D_ + c0)       = o0;
            *(float2*)(C + (size_t)(r0 + 8) * D_ + c0) = o1;
        }
    }
}

// ---------------------------------------------------------------------------
// Flash attention, fp32 SIMT. BQ=128 queries/block, BK=128 keys/tile.
// Scores stage:  16x16 threads, 8 q-rows x 8 k-cols each (BK=128 covered).
// PV/output:     16x16 threads, 8 q-rows x 4 d-cols each (HD=64 covered).
// Blended LDS traffic ~1.25 B/FMA.
// ---------------------------------------------------------------------------
#define BQ   128
#define BK   128
#define QP   132
#define KP   132
#define VP   68
#define PP   136
#define NKT  (S_ / BK)   // 16
// Qst 64*QP + union(Kst 64*KP = 8448, V 128*VP = 8704) + Ps 128*PP
#define FSMEM ((HD_ * QP + BK * VP + BQ * PP) * 4)   // 138240 B

__global__ __launch_bounds__(256, 1)
void flash_attn_kernel(const float* __restrict__ Qg, const float* __restrict__ Kg,
                       const float* __restrict__ Vg, float* __restrict__ Og)
{
    extern __shared__ float smf[];
    float* Qst = smf;                       // [64 d][BQ], stride QP
    float* KVs = smf + HD_ * QP;            // K^T [64][BK] (KP) OR V [BK][64] (VP)
    float* Ps  = smf + HD_ * QP + BK * VP;  // [BQ][BK], stride PP

    const int tid = threadIdx.x;
    const int tr = tid >> 4;    // q rows tr*8 .. +7
    const int tc = tid & 15;    // scores: k cols tc*8..+7 ; PV: d cols tc*4..+3
    const int qb = blockIdx.x * BQ;
    const int h  = blockIdx.y;
    const int b  = blockIdx.z;
    const size_t base = (size_t)b * S_ * D_ + (size_t)h * HD_;

    // Load Q tile transposed, folding in 1/sqrt(HD)=0.125
    {
        const int row = tid >> 1, half = tid & 1;
        const float* src = Qg + base + (size_t)(qb + row) * D_;
#pragma unroll
        for (int i = 0; i < 8; i++) {
            const int d0 = (half * 8 + i) * 4;
            float4 v = *(const float4*)(src + d0);
            Qst[(d0 + 0) * QP + row] = v.x * 0.125f;
            Qst[(d0 + 1) * QP + row] = v.y * 0.125f;
            Qst[(d0 + 2) * QP + row] = v.z * 0.125f;
            Qst[(d0 + 3) * QP + row] = v.w * 0.125f;
        }
    }

    float m[8], l[8], acc[8][4];
#pragma unroll
    for (int i = 0; i < 8; i++) {
        m[i] = -1e30f; l[i] = 0.f;
#pragma unroll
        for (int j = 0; j < 4; j++) acc[i][j] = 0.f;
    }

    for (int kt = 0; kt < NKT; kt++) {
        __syncthreads();  // prev iter's Ps/V reads done (Qst visible on kt=0)

        // K tile transposed into KVs: [64 d][128 rows] stride KP
        {
            const int row = tid >> 1, half = tid & 1;
            const float* src = Kg + base + (size_t)(kt * BK + row) * D_;
#pragma unroll
            for (int i = 0; i < 8; i++) {
                const int d0 = (half * 8 + i) * 4;
                float4 v = *(const float4*)(src + d0);
                KVs[(d0 + 0) * KP + row] = v.x;
                KVs[(d0 + 1) * KP + row] = v.y;
                KVs[(d0 + 2) * KP + row] = v.z;
                KVs[(d0 + 3) * KP + row] = v.w;
            }
        }
        __syncthreads();

        // Scores: s[i][j] = sum_d Qst[d][tr*8+i] * Kst[d][tc*8+j]
        float s[8][8];
#pragma unroll
        for (int i = 0; i < 8; i++)
#pragma unroll
            for (int j = 0; j < 8; j++) s[i][j] = 0.f;

#pragma unroll 2
        for (int d = 0; d < HD_; d++) {
            float a[8], bb[8];
            *(float4*)&a[0]  = *(const float4*)&Qst[d * QP + tr * 8];
            *(float4*)&a[4]  = *(const float4*)&Qst[d * QP + tr * 8 + 4];
            *(float4*)&bb[0] = *(const float4*)&KVs[d * KP + tc * 8];
            *(float4*)&bb[4] = *(const float4*)&KVs[d * KP + tc * 8 + 4];
#pragma unroll
            for (int i = 0; i < 8; i++)
#pragma unroll
                for (int j = 0; j < 8; j++)
                    s[i][j] += a[i] * bb[j];
        }

        // Online softmax per row (reduce across the 16 tc lanes of each tr group)
#pragma unroll
        for (int i = 0; i < 8; i++) {
            float mm = s[i][0];
#pragma unroll
            for (int j = 1; j < 8; j++) mm = fmaxf(mm, s[i][j]);
#pragma unroll
            for (int off = 1; off < 16; off <<= 1)
                mm = fmaxf(mm, __shfl_xor_sync(0xffffffffu, mm, off));
            const float mn = fmaxf(m[i], mm);
            const float alpha = __expf(m[i] - mn);
            m[i] = mn;
            l[i] *= alpha;
#pragma unroll
            for (int j = 0; j < 4; j++) acc[i][j] *= alpha;
            float ls = 0.f;
#pragma unroll
            for (int j = 0; j < 8; j++) {
                const float p = __expf(s[i][j] - mn);
                s[i][j] = p;
                ls += p;
            }
#pragma unroll
            for (int off = 1; off < 16; off <<= 1)
                ls += __shfl_xor_sync(0xffffffffu, ls, off);
            l[i] += ls;
            *(float4*)&Ps[(tr * 8 + i) * PP + tc * 8]     = *(float4*)&s[i][0];
            *(float4*)&Ps[(tr * 8 + i) * PP + tc * 8 + 4] = *(float4*)&s[i][4];
        }
        __syncthreads();  // Ps written; K reads done

        // V tile (natural layout [row][d], stride VP) into KVs
        {
            const int row = tid >> 1, half = tid & 1;
            const float* src = Vg + base + (size_t)(kt * BK + row) * D_ + half * 32;
            float* dst = KVs + row * VP + half * 32;
#pragma unroll
            for (int i = 0; i < 8; i++)
                *(float4*)(dst + i * 4) = *(const float4*)(src + i * 4);
        }
        __syncthreads();

        // acc[i][j] += sum_kk Ps[tr*8+i][kk] * V[kk][tc*4+j]   (j over HD cols)
#pragma unroll 2
        for (int kk0 = 0; kk0 < BK; kk0 += 4) {
            float p[8][4];
#pragma unroll
            for (int i = 0; i < 8; i++)
                *(float4*)p[i] = *(const float4*)&Ps[(tr * 8 + i) * PP + kk0];
#pragma unroll
            for (int u = 0; u < 4; u++) {
                float vv[4];
                *(float4*)vv = *(const float4*)&KVs[(kk0 + u) * VP + tc * 4];
#pragma unroll
                for (int i = 0; i < 8; i++)
#pragma unroll
                    for (int j = 0; j < 4; j++)
                        acc[i][j] += p[i][u] * vv[j];
            }
        }
    }

    // Normalize and write ctx (same [B,S,H,HD] layout); cols tc*4 .. +3 (HD=64)
#pragma unroll
    for (int i = 0; i < 8; i++) {
        const float inv = 1.f / l[i];
        float4 o;
        o.x = acc[i][0] * inv; o.y = acc[i][1] * inv;
        o.z = acc[i][2] * inv; o.w = acc[i][3] * inv;
        *(float4*)(Og + base + (size_t)(qb + tr * 8 + i) * D_ + tc * 4) = o;
    }
}

// ---------------------------------------------------------------------------
// Launch
// ---------------------------------------------------------------------------
extern "C" void kernel_launch(void* const* d_in, const int* in_sizes, int n_in,
                              void* d_out, int out_size)
{
    (void)in_sizes; (void)n_in; (void)out_size;
    const float* x  = (const float*)d_in[0];
    const float* Wq = (const float*)d_in[1];
    const float* bq = (const float*)d_in[2];
    const float* Wk = (const float*)d_in[3];
    const float* bk = (const float*)d_in[4];
    const float* Wv = (const float*)d_in[5];
    const float* bv = (const float*)d_in[6];
    const float* Wo = (const float*)d_in[7];
    const float* bo = (const float*)d_in[8];
    float* out = (float*)d_out;

    float *q, *k, *v, *ctx;
    __nv_bfloat16 *ahi, *alo, *bhi, *blo;
    cudaGetSymbolAddress((void**)&q,   g_q);
    cudaGetSymbolAddress((void**)&k,   g_k);
    cudaGetSymbolAddress((void**)&v,   g_v);
    cudaGetSymbolAddress((void**)&ctx, g_ctx);
    cudaGetSymbolAddress((void**)&ahi, g_ahi);
    cudaGetSymbolAddress((void**)&alo, g_alo);
    cudaGetSymbolAddress((void**)&bhi, g_bhi);
    cudaGetSymbolAddress((void**)&blo, g_blo);

    cudaFuncSetAttribute(flash_attn_kernel,
                         cudaFuncAttributeMaxDynamicSharedMemorySize, FSMEM);
    cudaFuncSetAttribute(gemm_mma_bf16x3,
                         cudaFuncAttributeMaxDynamicSharedMemorySize, G_SMEM);

    const dim3 wgrid(32, 32), wblk(32, 8);
    const dim3 ggrid(D_ / 128, M_ / 128);    // (8, 32)
    const int  sgrid = (M_ * D_) / (256 * 4);

    // activation split (x)
    split_act_kernel<<<sgrid, 256>>>(x, ahi, alo);

    // Q, K, V projections
    split_w_kernel<<<wgrid, wblk>>>(Wq, bhi, blo);
    gemm_mma_bf16x3<<<ggrid, 256, G_SMEM>>>(ahi, alo, bhi, blo, bq, q);
    split_w_kernel<<<wgrid, wblk>>>(Wk, bhi, blo);
    gemm_mma_bf16x3<<<ggrid, 256, G_SMEM>>>(ahi, alo, bhi, blo, bk, k);
    split_w_kernel<<<wgrid, wblk>>>(Wv, bhi, blo);
    gemm_mma_bf16x3<<<ggrid, 256, G_SMEM>>>(ahi, alo, bhi, blo, bv, v);

    // attention
    dim3 fg(S_ / BQ, H_, B_);   // (16, 16, 2)
    flash_attn_kernel<<<fg, 256, FSMEM>>>(q, k, v, ctx);

    // output projection
    split_act_kernel<<<sgrid, 256>>>(ctx, ahi, alo);
    split_w_kernel<<<wgrid, wblk>>>(Wo, bhi, blo);
    gemm_mma_bf16x3<<<ggrid, 256, G_SMEM>>>(ahi, alo, bhi, blo, bo, out);
}

// round 6
// speedup vs baseline: 1.1754x; 1.1754x over previous
#include <cuda_runtime.h>
#include <cuda_bf16.h>
#include <cstdint>

// Problem constants
#define B_  2
#define S_  2048
#define D_  1024
#define H_  16
#define HD_ 64
#define M_  (B_ * S_)          // 4096 tokens

// ---------------------------------------------------------------------------
// Scratch (allocation-free rule: __device__ globals)
// ---------------------------------------------------------------------------
__device__ float g_q[M_ * D_];
__device__ float g_k[M_ * D_];
__device__ float g_v[M_ * D_];
__device__ float g_ctx[M_ * D_];
__device__ __nv_bfloat16 g_ahi[M_ * D_];   // activation split hi  (x, then ctx)
__device__ __nv_bfloat16 g_alo[M_ * D_];   // activation split lo
__device__ __nv_bfloat16 g_bhi[D_ * D_];   // weight split hi, transposed [N,K]
__device__ __nv_bfloat16 g_blo[D_ * D_];   // weight split lo, transposed [N,K]

// ---------------------------------------------------------------------------
// PTX helpers (sm_80-era instructions only: compute_103 target rejects tcgen05)
// ---------------------------------------------------------------------------
__device__ __forceinline__ uint32_t smem_u32(const void* p) {
    uint32_t a;
    asm("{ .reg .u64 t; cvta.to.shared.u64 t, %1; cvt.u32.u64 %0, t; }" : "=r"(a) : "l"(p));
    return a;
}

__device__ __forceinline__ void ldsm_x4(uint32_t* r, uint32_t addr) {
    asm volatile("ldmatrix.sync.aligned.m8n8.x4.shared.b16 {%0,%1,%2,%3}, [%4];"
                 : "=r"(r[0]), "=r"(r[1]), "=r"(r[2]), "=r"(r[3]) : "r"(addr));
}

__device__ __forceinline__ void mma16816(float* c, const uint32_t* a,
                                         uint32_t b0, uint32_t b1) {
    asm volatile("mma.sync.aligned.m16n8k16.row.col.f32.bf16.bf16.f32 "
                 "{%0,%1,%2,%3}, {%4,%5,%6,%7}, {%8,%9}, {%0,%1,%2,%3};"
                 : "+f"(c[0]), "+f"(c[1]), "+f"(c[2]), "+f"(c[3])
                 : "r"(a[0]), "r"(a[1]), "r"(a[2]), "r"(a[3]), "r"(b0), "r"(b1));
}

__device__ __forceinline__ void cp16(uint32_t dst, const void* src) {
    asm volatile("cp.async.cg.shared.global [%0], [%1], 16;" :: "r"(dst), "l"(src) : "memory");
}
#define CP_COMMIT() asm volatile("cp.async.commit_group;" ::: "memory")
#define CP_WAIT0()  asm volatile("cp.async.wait_group 0;" ::: "memory")
#define CP_WAIT1()  asm volatile("cp.async.wait_group 1;" ::: "memory")

// ---------------------------------------------------------------------------
// Split kernels: fp32 -> (bf16 hi, bf16 lo), lo = bf16(x - float(hi))
// ---------------------------------------------------------------------------
__global__ __launch_bounds__(256)
void split_act_kernel(const float* __restrict__ in,
                      __nv_bfloat16* __restrict__ hi, __nv_bfloat16* __restrict__ lo)
{
    const int idx = (blockIdx.x * 256 + threadIdx.x) * 4;
    float4 v = *(const float4*)(in + idx);
    __nv_bfloat162 h01 = __floats2bfloat162_rn(v.x, v.y);
    __nv_bfloat162 h23 = __floats2bfloat162_rn(v.z, v.w);
    float2 f01 = __bfloat1622float2(h01);
    float2 f23 = __bfloat1622float2(h23);
    __nv_bfloat162 l01 = __floats2bfloat162_rn(v.x - f01.x, v.y - f01.y);
    __nv_bfloat162 l23 = __floats2bfloat162_rn(v.z - f23.x, v.w - f23.y);
    *(__nv_bfloat162*)(hi + idx)     = h01;
    *(__nv_bfloat162*)(hi + idx + 2) = h23;
    *(__nv_bfloat162*)(lo + idx)     = l01;
    *(__nv_bfloat162*)(lo + idx + 2) = l23;
}

// W[K=1024, N=1024] fp32 -> hi/lo [N, K] bf16 (transpose + split)
__global__ __launch_bounds__(256)
void split_w_kernel(const float* __restrict__ W,
                    __nv_bfloat16* __restrict__ hi, __nv_bfloat16* __restrict__ lo)
{
    __shared__ float t[32][33];
    const int tx = threadIdx.x, ty = threadIdx.y;      // 32 x 8
    const int n0 = blockIdx.x * 32, k0 = blockIdx.y * 32;
#pragma unroll
    for (int r = 0; r < 32; r += 8)
        t[ty + r][tx] = W[(size_t)(k0 + ty + r) * D_ + n0 + tx];
    __syncthreads();
#pragma unroll
    for (int r = 0; r < 32; r += 8) {
        const float v = t[tx][ty + r];
        const __nv_bfloat16 h = __float2bfloat16(v);
        const __nv_bfloat16 l = __float2bfloat16(v - __bfloat162float(h));
        const size_t o = (size_t)(n0 + ty + r) * D_ + k0 + tx;
        hi[o] = h; lo[o] = l;
    }
}

// ---------------------------------------------------------------------------
// mma.sync bf16x3 GEMM:  C[M,N] = Ahi@Bhi^T + Ahi@Blo^T + Alo@Bhi^T + bias
// CTA tile 128x128, BK=64, 512 threads (16 warps as 4m x 4n, warp tile 32x32),
// 2-stage cp.async pipeline. 16 resident warps/SM at occ 1 + overlap.
// ---------------------------------------------------------------------------
#define GSM_A_HI 0
#define GSM_A_LO 16384
#define GSM_B_HI 32768
#define GSM_B_LO 49152
#define G_STAGE  65536
#define G_SMEM   (2 * G_STAGE + 1024)

__global__ __launch_bounds__(512, 1)
void gemm_mma_bf16x3(const __nv_bfloat16* __restrict__ Ahi, const __nv_bfloat16* __restrict__ Alo,
                     const __nv_bfloat16* __restrict__ Bhi, const __nv_bfloat16* __restrict__ Blo,
                     const float* __restrict__ bias, float* __restrict__ C)
{
    extern __shared__ char smraw[];
    const uint32_t raw = smem_u32(smraw);
    const uint32_t org = (raw + 1023u) & ~1023u;      // 1024-aligned for swizzle

    const int tid  = threadIdx.x;
    const int lane = tid & 31;
    const int wid  = tid >> 5;            // 0..15
    const int wm   = wid >> 2;            // 0..3
    const int wn   = wid & 3;             // 0..3
    const int bm = blockIdx.y * 128, bn = blockIdx.x * 128;

    const int grp = lane >> 3, lr = lane & 7;

    // ldmatrix row-base offsets (relative; add stage + matrix offset at use)
    uint32_t a_base[2]; int a_xr[2];
#pragma unroll
    for (int mt = 0; mt < 2; mt++) {
        const int r = wm * 32 + mt * 16 + ((grp & 1) << 3) + lr;
        a_base[mt] = org + (uint32_t)(r << 7);
        a_xr[mt] = r & 7;
    }
    const int cA = grp >> 1;

    uint32_t b_base[2]; int b_xr[2];
#pragma unroll
    for (int np = 0; np < 2; np++) {
        const int r = wn * 32 + np * 16 + ((grp >> 1) << 3) + lr;
        b_base[np] = org + (uint32_t)(r << 7);
        b_xr[np] = r & 7;
    }
    const int cB = grp & 1;

    float acc[2][4][4];
#pragma unroll
    for (int i = 0; i < 2; i++)
#pragma unroll
        for (int j = 0; j < 4; j++)
#pragma unroll
            for (int q = 0; q < 4; q++) acc[i][j][q] = 0.f;

    // cp.async store-side constants: 512 threads, each 2 rows per tile
    const int srow0 = tid >> 3;            // 0..63 ; + 64*i
    const int scol  = tid & 7;             // 16B chunk
    const uint32_t cxor = (uint32_t)((scol ^ ((tid >> 3) & 7)) << 4);

#define G_ISSUE(KT) do {                                                       \
    const int _k0 = (KT) * 64;                                                 \
    const uint32_t stg = org + ((KT) & 1) * G_STAGE;                           \
    _Pragma("unroll")                                                          \
    for (int i = 0; i < 2; i++) {                                              \
        const int row = srow0 + 64 * i;                                        \
        const uint32_t doff = (uint32_t)(row << 7) + cxor;                     \
        const size_t ea = (size_t)(bm + row) * D_ + _k0 + scol * 8;            \
        const size_t eb = (size_t)(bn + row) * D_ + _k0 + scol * 8;            \
        cp16(stg + GSM_A_HI + doff, Ahi + ea);                                 \
        cp16(stg + GSM_A_LO + doff, Alo + ea);                                 \
        cp16(stg + GSM_B_HI + doff, Bhi + eb);                                 \
        cp16(stg + GSM_B_LO + doff, Blo + eb);                                 \
    }                                                                          \
    CP_COMMIT();                                                               \
} while (0)

    G_ISSUE(0);

    for (int kt = 0; kt < 16; kt++) {
        if (kt < 15) { G_ISSUE(kt + 1); CP_WAIT1(); }
        else         { CP_WAIT0(); }
        __syncthreads();

        const uint32_t stg = (uint32_t)((kt & 1) * G_STAGE);
#pragma unroll
        for (int t = 0; t < 3; t++) {
            const uint32_t aoff = stg + ((t == 2) ? GSM_A_LO : GSM_A_HI);
            const uint32_t boff = stg + ((t == 1) ? GSM_B_LO : GSM_B_HI);
#pragma unroll
            for (int ks = 0; ks < 4; ks++) {
                uint32_t af[2][4];
#pragma unroll
                for (int mt = 0; mt < 2; mt++) {
                    const int cc = ks * 2 + cA;
                    ldsm_x4(af[mt], a_base[mt] + aoff + (uint32_t)((cc ^ a_xr[mt]) << 4));
                }
                uint32_t bf[2][4];
#pragma unroll
                for (int np = 0; np < 2; np++) {
                    const int cc = ks * 2 + cB;
                    ldsm_x4(bf[np], b_base[np] + boff + (uint32_t)((cc ^ b_xr[np]) << 4));
                }
#pragma unroll
                for (int mt = 0; mt < 2; mt++)
#pragma unroll
                    for (int nt = 0; nt < 4; nt++)
                        mma16816(acc[mt][nt], af[mt],
                                 bf[nt >> 1][(nt & 1) * 2], bf[nt >> 1][(nt & 1) * 2 + 1]);
            }
        }
        __syncthreads();   // compute done before issue overwrites this stage
    }

    // Epilogue: fragment -> gmem with bias
#pragma unroll
    for (int mt = 0; mt < 2; mt++) {
        const int r0 = bm + wm * 32 + mt * 16 + (lane >> 2);
#pragma unroll
        for (int nt = 0; nt < 4; nt++) {
            const int c0 = bn + wn * 32 + nt * 8 + ((lane & 3) << 1);
            const float bx = bias[c0], by = bias[c0 + 1];
            float2 o0, o1;
            o0.x = acc[mt][nt][0] + bx; o0.y = acc[mt][nt][1] + by;
            o1.x = acc[mt][nt][2] + bx; o1.y = acc[mt][nt][3] + by;
            *(float2*)(C + (size_t)r0 * D_ + c0)       = o0;
            *(float2*)(C + (size_t)(r0 + 8) * D_ + c0) = o1;
        }
    }
}

// ---------------------------------------------------------------------------
// Flash attention, fp32 SIMT (exact round-3 kernel: BQ=128, BK=64, occ 2).
// ---------------------------------------------------------------------------
#define BQ   128
#define BK   64
#define QP   132
#define KP   68
#define NKT  (S_ / BK)   // 32
#define FSMEM ((HD_ * QP + BK * KP + BQ * KP) * 4)   // 86016 B

__global__ __launch_bounds__(256, 2)
void flash_attn_kernel(const float* __restrict__ Qg, const float* __restrict__ Kg,
                       const float* __restrict__ Vg, float* __restrict__ Og)
{
    extern __shared__ float smf[];
    float* Qst = smf;                    // [64 d][128 rows], stride QP
    float* KVs = smf + HD_ * QP;         // K^T [64 d][64 rows] OR V [64 rows][64 d], stride KP
    float* Ps  = smf + HD_ * QP + BK * KP;  // [128 rows][64 cols], stride KP

    const int tid = threadIdx.x;
    const int tr = tid >> 4;    // 0..15 -> q rows tr*8 .. tr*8+7
    const int tc = tid & 15;    // 0..15 -> k cols tc*4 .. tc*4+3
    const int qb = blockIdx.x * BQ;
    const int h  = blockIdx.y;
    const int b  = blockIdx.z;
    const size_t base = (size_t)b * S_ * D_ + (size_t)h * HD_;

    // Load Q tile transposed, folding in 1/sqrt(HD)=0.125
    {
        const int row = tid >> 1, half = tid & 1;
        const float* src = Qg + base + (size_t)(qb + row) * D_;
#pragma unroll
        for (int i = 0; i < 8; i++) {
            const int d0 = (half * 8 + i) * 4;
            float4 v = *(const float4*)(src + d0);
            Qst[(d0 + 0) * QP + row] = v.x * 0.125f;
            Qst[(d0 + 1) * QP + row] = v.y * 0.125f;
            Qst[(d0 + 2) * QP + row] = v.z * 0.125f;
            Qst[(d0 + 3) * QP + row] = v.w * 0.125f;
        }
    }

    float m[8], l[8], acc[8][4];
#pragma unroll
    for (int i = 0; i < 8; i++) {
        m[i] = -1e30f; l[i] = 0.f;
#pragma unroll
        for (int j = 0; j < 4; j++) acc[i][j] = 0.f;
    }

    for (int kt = 0; kt < NKT; kt++) {
        __syncthreads();  // prev iter's Ps/V reads done (Qst visible on kt=0)

        // K tile transposed into KVs
        {
            const int row = tid >> 2, qd = tid & 3;
            const float* src = Kg + base + (size_t)(kt * BK + row) * D_;
#pragma unroll
            for (int i = 0; i < 4; i++) {
                const int d0 = (qd + 4 * i) * 4;
                float4 v = *(const float4*)(src + d0);
                KVs[(d0 + 0) * KP + row] = v.x;
                KVs[(d0 + 1) * KP + row] = v.y;
                KVs[(d0 + 2) * KP + row] = v.z;
                KVs[(d0 + 3) * KP + row] = v.w;
            }
        }
        __syncthreads();

        // Scores: s[i][j] = sum_d Qst[d][tr*8+i] * Kst[d][tc*4+j]
        float s[8][4];
#pragma unroll
        for (int i = 0; i < 8; i++)
#pragma unroll
            for (int j = 0; j < 4; j++) s[i][j] = 0.f;

#pragma unroll 4
        for (int d = 0; d < HD_; d++) {
            float a[8], bb[4];
            *(float4*)&a[0] = *(const float4*)&Qst[d * QP + tr * 8];
            *(float4*)&a[4] = *(const float4*)&Qst[d * QP + tr * 8 + 4];
            *(float4*)bb    = *(const float4*)&KVs[d * KP + tc * 4];
#pragma unroll
            for (int i = 0; i < 8; i++)
#pragma unroll
                for (int j = 0; j < 4; j++)
                    s[i][j] += a[i] * bb[j];
        }

        // Online softmax per row (reduce across the 16 tc lanes of each tr group)
#pragma unroll
        for (int i = 0; i < 8; i++) {
            float mm = fmaxf(fmaxf(s[i][0], s[i][1]), fmaxf(s[i][2], s[i][3]));
#pragma unroll
            for (int off = 1; off < 16; off <<= 1)
                mm = fmaxf(mm, __shfl_xor_sync(0xffffffffu, mm, off));
            const float mn = fmaxf(m[i], mm);
            const float alpha = __expf(m[i] - mn);
            m[i] = mn;
            l[i] *= alpha;
#pragma unroll
            for (int j = 0; j < 4; j++) acc[i][j] *= alpha;
            float ls = 0.f;
#pragma unroll
            for (int j = 0; j < 4; j++) {
                const float p = __expf(s[i][j] - mn);
                s[i][j] = p;
                ls += p;
            }
#pragma unroll
            for (int off = 1; off < 16; off <<= 1)
                ls += __shfl_xor_sync(0xffffffffu, ls, off);
            l[i] += ls;
            *(float4*)&Ps[(tr * 8 + i) * KP + tc * 4] =
                make_float4(s[i][0], s[i][1], s[i][2], s[i][3]);
        }
        __syncthreads();  // Ps written; K reads done

        // V tile (natural layout) into KVs
        {
            const int row = tid >> 2, qd = tid & 3;
            const float* src = Vg + base + (size_t)(kt * BK + row) * D_;
#pragma unroll
            for (int i = 0; i < 4; i++) {
                const int d0 = (qd + 4 * i) * 4;
                *(float4*)&KVs[row * KP + d0] = *(const float4*)(src + d0);
            }
        }
        __syncthreads();

        // acc[i][j] += sum_kk Ps[tr*8+i][kk] * V[kk][tc*4+j]
#pragma unroll 2
        for (int kk0 = 0; kk0 < BK; kk0 += 4) {
            float p[8][4];
#pragma unroll
            for (int i = 0; i < 8; i++)
                *(float4*)p[i] = *(const float4*)&Ps[(tr * 8 + i) * KP + kk0];
#pragma unroll
            for (int u = 0; u < 4; u++) {
                float vv[4];
                *(float4*)vv = *(const float4*)&KVs[(kk0 + u) * KP + tc * 4];
#pragma unroll
                for (int i = 0; i < 8; i++)
#pragma unroll
                    for (int j = 0; j < 4; j++)
                        acc[i][j] += p[i][u] * vv[j];
            }
        }
    }

    // Normalize and write ctx (same [B,S,H,HD] layout)
#pragma unroll
    for (int i = 0; i < 8; i++) {
        const float inv = 1.f / l[i];
        float4 o;
        o.x = acc[i][0] * inv; o.y = acc[i][1] * inv;
        o.z = acc[i][2] * inv; o.w = acc[i][3] * inv;
        *(float4*)(Og + base + (size_t)(qb + tr * 8 + i) * D_ + tc * 4) = o;
    }
}

// ---------------------------------------------------------------------------
// Launch
// ---------------------------------------------------------------------------
extern "C" void kernel_launch(void* const* d_in, const int* in_sizes, int n_in,
                              void* d_out, int out_size)
{
    (void)in_sizes; (void)n_in; (void)out_size;
    const float* x  = (const float*)d_in[0];
    const float* Wq = (const float*)d_in[1];
    const float* bq = (const float*)d_in[2];
    const float* Wk = (const float*)d_in[3];
    const float* bk = (const float*)d_in[4];
    const float* Wv = (const float*)d_in[5];
    const float* bv = (const float*)d_in[6];
    const float* Wo = (const float*)d_in[7];
    const float* bo = (const float*)d_in[8];
    float* out = (float*)d_out;

    float *q, *k, *v, *ctx;
    __nv_bfloat16 *ahi, *alo, *bhi, *blo;
    cudaGetSymbolAddress((void**)&q,   g_q);
    cudaGetSymbolAddress((void**)&k,   g_k);
    cudaGetSymbolAddress((void**)&v,   g_v);
    cudaGetSymbolAddress((void**)&ctx, g_ctx);
    cudaGetSymbolAddress((void**)&ahi, g_ahi);
    cudaGetSymbolAddress((void**)&alo, g_alo);
    cudaGetSymbolAddress((void**)&bhi, g_bhi);
    cudaGetSymbolAddress((void**)&blo, g_blo);

    cudaFuncSetAttribute(flash_attn_kernel,
                         cudaFuncAttributeMaxDynamicSharedMemorySize, FSMEM);
    cudaFuncSetAttribute(gemm_mma_bf16x3,
                         cudaFuncAttributeMaxDynamicSharedMemorySize, G_SMEM);

    const dim3 wgrid(32, 32), wblk(32, 8);
    const dim3 ggrid(D_ / 128, M_ / 128);    // (8, 32)
    const int  sgrid = (M_ * D_) / (256 * 4);

    // activation split (x)
    split_act_kernel<<<sgrid, 256>>>(x, ahi, alo);

    // Q, K, V projections
    split_w_kernel<<<wgrid, wblk>>>(Wq, bhi, blo);
    gemm_mma_bf16x3<<<ggrid, 512, G_SMEM>>>(ahi, alo, bhi, blo, bq, q);
    split_w_kernel<<<wgrid, wblk>>>(Wk, bhi, blo);
    gemm_mma_bf16x3<<<ggrid, 512, G_SMEM>>>(ahi, alo, bhi, blo, bk, k);
    split_w_kernel<<<wgrid, wblk>>>(Wv, bhi, blo);
    gemm_mma_bf16x3<<<ggrid, 512, G_SMEM>>>(ahi, alo, bhi, blo, bv, v);

    // attention
    dim3 fg(S_ / BQ, H_, B_);   // (16, 16, 2)
    flash_attn_kernel<<<fg, 256, FSMEM>>>(q, k, v, ctx);

    // output projection
    split_act_kernel<<<sgrid, 256>>>(ctx, ahi, alo);
    split_w_kernel<<<wgrid, wblk>>>(Wo, bhi, blo);
    gemm_mma_bf16x3<<<ggrid, 512, G_SMEM>>>(ahi, alo, bhi, blo, bo, out);
}